// round 1
// baseline (speedup 1.0000x reference)
#include <cuda_runtime.h>
#include <cstdint>
#include <cstddef>

// ---------------------------------------------------------------------------
// FlowEncoder: two-image conv backbone -> correlation volume -> fusion convs
// -> global average pool. All fp32 direct convolution, BN folded, ReLU fused.
// ---------------------------------------------------------------------------

#define EPS_BN 1e-5f
#define EPS_L2 1e-12f

// dims
#define B       32
#define N2      64              // both images as batch
#define H0      384
#define W0      512
#define H1      192
#define W1      256
#define H2      96
#define W2      128
#define H3      48
#define W3      64
#define H4      24
#define W4      32
#define HP      56              // H3 + 2*4
#define WP      72              // W3 + 2*4
#define CCAT    209             // 81 + 128

// scratch (device-global; static allocation allowed)
__device__ float g_img  [(size_t)N2 * 3   * H0 * W0];   // 37.7M
__device__ float g_feat1[(size_t)N2 * 32  * H1 * W1];   // 100.7M
__device__ float g_feat2[(size_t)N2 * 64  * H2 * W2];   // 50.3M
__device__ float g_feat3[(size_t)N2 * 128 * H3 * W3];   // 25.2M
__device__ float g_f0n  [(size_t)B  * 128 * HP * WP];   // padded+normalized f0
__device__ float g_f1n  [(size_t)B  * 128 * H3 * W3];
__device__ float g_cat  [(size_t)B  * CCAT* H3 * W3];
__device__ float g_x1   [(size_t)B  * 256 * H4 * W4];
__device__ float g_x2   [(size_t)B  * 256 * H4 * W4];

// ---------------------------------------------------------------------------
// concat img0,img1 into batch-64 buffer
// ---------------------------------------------------------------------------
__global__ void __launch_bounds__(256) copy_imgs_kernel(
    const float* __restrict__ a, const float* __restrict__ b)
{
    const size_t N1 = (size_t)B * 3 * H0 * W0;
    size_t i = (size_t)blockIdx.x * blockDim.x + threadIdx.x;
    if (i < N1)           g_img[i] = a[i];
    else if (i < 2 * N1)  g_img[i] = b[i - N1];
}

// ---------------------------------------------------------------------------
// Generic direct conv + BN + ReLU. Block: TH rows x Wout cols of one output
// channel; weights for that channel staged in SMEM.
// grid = (Hout/TH, Cout, N), blockDim = TH*Wout
// ---------------------------------------------------------------------------
template<int Cin, int Cout, int K, int S, int P,
         int Hin, int Win, int Hout, int Wout, int TH>
__global__ void __launch_bounds__(TH * Wout) conv_bn_relu_kernel(
    const float* __restrict__ src, float* __restrict__ dst,
    const float* __restrict__ w,  const float* __restrict__ bb,
    const float* __restrict__ g,  const float* __restrict__ be,
    const float* __restrict__ m,  const float* __restrict__ v)
{
    __shared__ float sw[Cin * K * K];
    const int c = blockIdx.y;
    const int n = blockIdx.z;

    const float* wp = w + (size_t)c * Cin * K * K;
    for (int i = threadIdx.x; i < Cin * K * K; i += blockDim.x) sw[i] = wp[i];
    __syncthreads();

    const float s    = g[c] * rsqrtf(v[c] + EPS_BN);
    const float bias = fmaf(bb[c] - m[c], s, be[c]);

    const int hh = blockIdx.x * TH + threadIdx.x / Wout;
    const int ww = threadIdx.x % Wout;

    const float* sp = src + (size_t)n * Cin * Hin * Win;
    const int ih0 = hh * S - P;
    const int iw0 = ww * S - P;

    float acc = 0.f;
    for (int ci = 0; ci < Cin; ci++) {
        const float* spc = sp + (size_t)ci * Hin * Win;
        const float* swc = sw + ci * K * K;
        #pragma unroll
        for (int kh = 0; kh < K; kh++) {
            const int ih = ih0 + kh;
            if ((unsigned)ih < (unsigned)Hin) {
                #pragma unroll
                for (int kw = 0; kw < K; kw++) {
                    const int iw = iw0 + kw;
                    if ((unsigned)iw < (unsigned)Win)
                        acc = fmaf(spc[ih * Win + iw], swc[kh * K + kw], acc);
                }
            }
        }
    }
    dst[((size_t)n * Cout + c) * (Hout * Wout) + hh * Wout + ww] =
        fmaxf(fmaf(acc, s, bias), 0.f);
}

// ---------------------------------------------------------------------------
// L2 normalize f1 over channels: (n in [32,64) of g_feat3) -> g_f1n
// ---------------------------------------------------------------------------
__global__ void __launch_bounds__(256) l2norm_f1_kernel()
{
    const int HW = H3 * W3;
    int idx = blockIdx.x * blockDim.x + threadIdx.x;
    if (idx >= B * HW) return;
    const int hw = idx % HW;
    const int n  = idx / HW;
    const float* p = g_feat3 + ((size_t)(n + B) * 128) * HW + hw;
    float ss = 0.f;
    #pragma unroll 8
    for (int c = 0; c < 128; c++) { float x = p[(size_t)c * HW]; ss = fmaf(x, x, ss); }
    const float inv = 1.f / fmaxf(sqrtf(ss), EPS_L2);
    float* o = g_f1n + ((size_t)n * 128) * HW + hw;
    #pragma unroll 8
    for (int c = 0; c < 128; c++) o[(size_t)c * HW] = p[(size_t)c * HW] * inv;
}

// L2 normalize f0 and scatter into 4-padded buffer (pad region stays zero —
// g_f0n is zero-initialized at module load and the pad cells are never written)
__global__ void __launch_bounds__(256) l2norm_f0_pad_kernel()
{
    const int HW = H3 * W3;
    int idx = blockIdx.x * blockDim.x + threadIdx.x;
    if (idx >= B * HW) return;
    const int hw = idx % HW;
    const int n  = idx / HW;
    const int h  = hw / W3;
    const int w  = hw % W3;
    const float* p = g_feat3 + ((size_t)n * 128) * HW + hw;   // f0 = first 32
    float ss = 0.f;
    #pragma unroll 8
    for (int c = 0; c < 128; c++) { float x = p[(size_t)c * HW]; ss = fmaf(x, x, ss); }
    const float inv = 1.f / fmaxf(sqrtf(ss), EPS_L2);
    float* o = g_f0n + ((size_t)n * 128 * HP + (h + 4)) * WP + (w + 4);
    #pragma unroll 8
    for (int c = 0; c < 128; c++) o[(size_t)c * HP * WP] = p[(size_t)c * HW] * inv;
}

// ---------------------------------------------------------------------------
// Correlation volume -> g_cat channels [0,81).
// Block handles (n, h, 32-wide w-tile); f1 tile and one padded f0 row in SMEM.
// ---------------------------------------------------------------------------
__global__ void __launch_bounds__(256) corr_kernel()
{
    __shared__ float s1[128 * 32];   // [c][w]
    __shared__ float s0[128 * 40];   // [c][w+dx window]
    const int wb = blockIdx.x * 32;
    const int h  = blockIdx.y;
    const int n  = blockIdx.z;
    const int tid = threadIdx.x;

    for (int i = tid; i < 128 * 32; i += 256) {
        const int c = i >> 5, w = i & 31;
        s1[i] = g_f1n[(((size_t)n * 128 + c) * H3 + h) * W3 + wb + w];
    }
    for (int dy = 0; dy < 9; dy++) {
        __syncthreads();
        for (int i = tid; i < 128 * 40; i += 256) {
            const int c = i / 40, w = i % 40;
            s0[i] = g_f0n[(((size_t)n * 128 + c) * HP + h + dy) * WP + wb + w];
        }
        __syncthreads();
        for (int it = tid; it < 288; it += 256) {
            const int dx = it >> 5, j = it & 31;
            float acc = 0.f;
            #pragma unroll 8
            for (int c = 0; c < 128; c++)
                acc = fmaf(s0[c * 40 + j + dx], s1[c * 32 + j], acc);
            g_cat[(((size_t)n * CCAT + dy * 9 + dx) * H3 + h) * W3 + wb + j] = acc;
        }
    }
}

// copy raw f1 into g_cat channels [81,209)
__global__ void __launch_bounds__(256) copy_f1_kernel()
{
    const int HW = H3 * W3;
    size_t i = (size_t)blockIdx.x * blockDim.x + threadIdx.x;
    if (i >= (size_t)B * 128 * HW) return;
    const size_t hw = i % HW;
    const size_t c  = (i / HW) % 128;
    const size_t n  = i / ((size_t)128 * HW);
    g_cat[((n * CCAT) + 81 + c) * HW + hw] =
        g_feat3[((n + B) * 128 + c) * HW + hw];
}

// ---------------------------------------------------------------------------
// SMEM-chunked conv: block computes COTILE output channels over the whole
// 24x32 plane (3 px/thread), streaming CITILE input channels through SMEM.
// grid = (Cout/COTILE, N), blockDim = 256. Requires Hout*Wout == 768.
// ---------------------------------------------------------------------------
template<int Cin, int Cout, int K, int S, int P,
         int Hin, int Win, int Hout, int Wout, int CITILE, int COTILE>
__global__ void __launch_bounds__(256) conv_chunked_kernel(
    const float* __restrict__ src, float* __restrict__ dst,
    const float* __restrict__ w,  const float* __restrict__ bb,
    const float* __restrict__ g,  const float* __restrict__ be,
    const float* __restrict__ m,  const float* __restrict__ v)
{
    constexpr int HW   = Hout * Wout;       // 768
    constexpr int NPIX = HW / 256;          // 3
    __shared__ float sin_s[CITILE * Hin * Win];
    __shared__ float swt_s[COTILE * CITILE * K * K];

    const int n   = blockIdx.y;
    const int co0 = blockIdx.x * COTILE;
    const int tid = threadIdx.x;

    int hh[NPIX], ww[NPIX];
    #pragma unroll
    for (int pi = 0; pi < NPIX; pi++) {
        const int p = tid + pi * 256;
        hh[pi] = p / Wout; ww[pi] = p % Wout;
    }

    float acc[COTILE][NPIX];
    #pragma unroll
    for (int co = 0; co < COTILE; co++)
        #pragma unroll
        for (int pi = 0; pi < NPIX; pi++) acc[co][pi] = 0.f;

    constexpr int NCH = (Cin + CITILE - 1) / CITILE;
    for (int ch = 0; ch < NCH; ch++) {
        const int ci0 = ch * CITILE;
        for (int i = tid; i < CITILE * Hin * Win; i += 256) {
            const int ci  = i / (Hin * Win);
            const int gci = ci0 + ci;
            sin_s[i] = (gci < Cin)
                ? src[((size_t)n * Cin + gci) * (Hin * Win) + (i % (Hin * Win))]
                : 0.f;
        }
        for (int i = tid; i < COTILE * CITILE * K * K; i += 256) {
            const int co  = i / (CITILE * K * K);
            const int r   = i % (CITILE * K * K);
            const int ci  = r / (K * K);
            const int kk  = r % (K * K);
            const int gci = ci0 + ci;
            swt_s[i] = (gci < Cin)
                ? w[(((size_t)(co0 + co)) * Cin + gci) * (K * K) + kk]
                : 0.f;
        }
        __syncthreads();

        for (int ci = 0; ci < CITILE; ci++) {
            const float* sp = sin_s + ci * Hin * Win;
            #pragma unroll
            for (int kh = 0; kh < K; kh++) {
                #pragma unroll
                for (int kw = 0; kw < K; kw++) {
                    float xin[NPIX];
                    #pragma unroll
                    for (int pi = 0; pi < NPIX; pi++) {
                        const int ih = hh[pi] * S - P + kh;
                        const int iw = ww[pi] * S - P + kw;
                        xin[pi] = ((unsigned)ih < (unsigned)Hin &&
                                   (unsigned)iw < (unsigned)Win)
                                  ? sp[ih * Win + iw] : 0.f;
                    }
                    #pragma unroll
                    for (int co = 0; co < COTILE; co++) {
                        const float wv = swt_s[(co * CITILE + ci) * (K * K) + kh * K + kw];
                        #pragma unroll
                        for (int pi = 0; pi < NPIX; pi++)
                            acc[co][pi] = fmaf(xin[pi], wv, acc[co][pi]);
                    }
                }
            }
        }
        __syncthreads();
    }

    #pragma unroll
    for (int co = 0; co < COTILE; co++) {
        const int c = co0 + co;
        const float s    = g[c] * rsqrtf(v[c] + EPS_BN);
        const float bias = fmaf(bb[c] - m[c], s, be[c]);
        #pragma unroll
        for (int pi = 0; pi < NPIX; pi++)
            dst[((size_t)n * Cout + c) * HW + hh[pi] * Wout + ww[pi]] =
                fmaxf(fmaf(acc[co][pi], s, bias), 0.f);
    }
}

// ---------------------------------------------------------------------------
// global average pool: (32,256,24,32) -> (32,256)
// ---------------------------------------------------------------------------
__global__ void __launch_bounds__(256) avgpool_kernel(float* __restrict__ out)
{
    __shared__ float red[256];
    const int b = blockIdx.x;                // n*256 + c
    const float* p = g_x2 + (size_t)b * (H4 * W4);
    float s = 0.f;
    for (int i = threadIdx.x; i < H4 * W4; i += 256) s += p[i];
    red[threadIdx.x] = s;
    __syncthreads();
    for (int st = 128; st > 0; st >>= 1) {
        if (threadIdx.x < st) red[threadIdx.x] += red[threadIdx.x + st];
        __syncthreads();
    }
    if (threadIdx.x == 0) out[b] = red[0] * (1.f / (H4 * W4));
}

// ---------------------------------------------------------------------------
extern "C" void kernel_launch(void* const* d_in, const int* in_sizes, int n_in,
                              void* d_out, int out_size)
{
    const float* img0 = (const float*)d_in[0];
    const float* img1 = (const float*)d_in[1];
    const float* w1  = (const float*)d_in[2];  const float* b1  = (const float*)d_in[3];
    const float* g1  = (const float*)d_in[4];  const float* be1 = (const float*)d_in[5];
    const float* m1  = (const float*)d_in[6];  const float* v1  = (const float*)d_in[7];
    const float* w2  = (const float*)d_in[8];  const float* b2  = (const float*)d_in[9];
    const float* g2  = (const float*)d_in[10]; const float* be2 = (const float*)d_in[11];
    const float* m2  = (const float*)d_in[12]; const float* v2  = (const float*)d_in[13];
    const float* w3  = (const float*)d_in[14]; const float* b3  = (const float*)d_in[15];
    const float* g3  = (const float*)d_in[16]; const float* be3 = (const float*)d_in[17];
    const float* m3  = (const float*)d_in[18]; const float* v3  = (const float*)d_in[19];
    const float* wf1 = (const float*)d_in[20]; const float* bf1 = (const float*)d_in[21];
    const float* gf1 = (const float*)d_in[22]; const float* bef1= (const float*)d_in[23];
    const float* mf1 = (const float*)d_in[24]; const float* vf1 = (const float*)d_in[25];
    const float* wf2 = (const float*)d_in[26]; const float* bf2 = (const float*)d_in[27];
    const float* gf2 = (const float*)d_in[28]; const float* bef2= (const float*)d_in[29];
    const float* mf2 = (const float*)d_in[30]; const float* vf2 = (const float*)d_in[31];
    float* out = (float*)d_out;

    float *p_img, *p_f1, *p_f2, *p_f3, *p_cat, *p_x1, *p_x2;
    cudaGetSymbolAddress((void**)&p_img, g_img);
    cudaGetSymbolAddress((void**)&p_f1,  g_feat1);
    cudaGetSymbolAddress((void**)&p_f2,  g_feat2);
    cudaGetSymbolAddress((void**)&p_f3,  g_feat3);
    cudaGetSymbolAddress((void**)&p_cat, g_cat);
    cudaGetSymbolAddress((void**)&p_x1,  g_x1);
    cudaGetSymbolAddress((void**)&p_x2,  g_x2);

    // 1. concat images into batch-64 buffer
    {
        const size_t tot = (size_t)N2 * 3 * H0 * W0;
        copy_imgs_kernel<<<(unsigned)((tot + 255) / 256), 256>>>(img0, img1);
    }

    // 2. backbone
    conv_bn_relu_kernel<3, 32, 7, 2, 3, H0, W0, H1, W1, 1>
        <<<dim3(H1 / 1, 32, N2), 1 * W1>>>(p_img, p_f1, w1, b1, g1, be1, m1, v1);
    conv_bn_relu_kernel<32, 64, 5, 2, 2, H1, W1, H2, W2, 2>
        <<<dim3(H2 / 2, 64, N2), 2 * W2>>>(p_f1, p_f2, w2, b2, g2, be2, m2, v2);
    conv_bn_relu_kernel<64, 128, 3, 2, 1, H2, W2, H3, W3, 4>
        <<<dim3(H3 / 4, 128, N2), 4 * W3>>>(p_f2, p_f3, w3, b3, g3, be3, m3, v3);

    // 3. l2norm + correlation + concat
    {
        const int tot = B * H3 * W3;
        l2norm_f1_kernel<<<(tot + 255) / 256, 256>>>();
        l2norm_f0_pad_kernel<<<(tot + 255) / 256, 256>>>();
    }
    corr_kernel<<<dim3(W3 / 32, H3, B), 256>>>();
    {
        const size_t tot = (size_t)B * 128 * H3 * W3;
        copy_f1_kernel<<<(unsigned)((tot + 255) / 256), 256>>>();
    }

    // 4. fusion convs
    conv_chunked_kernel<CCAT, 256, 3, 2, 1, H3, W3, H4, W4, 2, 8>
        <<<dim3(256 / 8, B), 256>>>(p_cat, p_x1, wf1, bf1, gf1, bef1, mf1, vf1);
    conv_chunked_kernel<256, 256, 3, 1, 1, H4, W4, H4, W4, 8, 8>
        <<<dim3(256 / 8, B), 256>>>(p_x1, p_x2, wf2, bf2, gf2, bef2, mf2, vf2);

    // 5. global average pool -> (32,256)
    avgpool_kernel<<<B * 256, 256>>>(out);
}

// round 2
// speedup vs baseline: 3.4688x; 3.4688x over previous
#include <cuda_runtime.h>
#include <cstdint>
#include <cstddef>

// ---------------------------------------------------------------------------
// FlowEncoder: register-tiled fp32 direct conv pipeline, BN folded, ReLU fused.
// ---------------------------------------------------------------------------

#define EPS_BN 1e-5f
#define EPS_L2 1e-12f

// dims
#define B       32
#define N2      64              // both images as batch
#define H0      384
#define W0      512
#define H1      192
#define W1      256
#define H2      96
#define W2      128
#define H3      48
#define W3      64
#define H4      24
#define W4      32
#define HP      56              // H3 + 2*4
#define WP      72              // W3 + 2*4
#define CCAT    209             // 81 + 128

// scratch (device-global; static allocation allowed)
__device__ float g_img  [(size_t)N2 * 3   * H0 * W0];
__device__ float g_feat1[(size_t)N2 * 32  * H1 * W1];
__device__ float g_feat2[(size_t)N2 * 64  * H2 * W2];
__device__ float g_feat3[(size_t)N2 * 128 * H3 * W3];
__device__ float g_f0n  [(size_t)B  * 128 * HP * WP];
__device__ float g_f1n  [(size_t)B  * 128 * H3 * W3];
__device__ float g_cat  [(size_t)B  * CCAT* H3 * W3];
__device__ float g_x1   [(size_t)B  * 256 * H4 * W4];
__device__ float g_x2   [(size_t)B  * 256 * H4 * W4];

// ---------------------------------------------------------------------------
// concat img0,img1 into batch-64 buffer
// ---------------------------------------------------------------------------
__global__ void __launch_bounds__(256) copy_imgs_kernel(
    const float* __restrict__ a, const float* __restrict__ b)
{
    const size_t N1 = (size_t)B * 3 * H0 * W0;
    size_t i = (size_t)blockIdx.x * blockDim.x + threadIdx.x;
    if (i < N1)           g_img[i] = a[i];
    else if (i < 2 * N1)  g_img[i] = b[i - N1];
}

// ---------------------------------------------------------------------------
// Register-tiled conv + BN + ReLU.
// Output tile: TH rows x 32 cols x CO channels per block. 256 threads.
// Thread = (pg = w-col, cg = channel group of NO=CO/8). Each thread computes
// TH pixels (same column, TH rows) x NO channels -> NO*TH accumulators.
// Input channel-chunk (CI) + weights staged in SMEM; borders zero-filled so
// the compute loop has NO conditionals. Weight reads are warp-uniform
// (broadcast); x reads are stride-S (<=2-way conflict).
// grid = ((Hout/TH)*(Wout/32), Cout/CO, N)
// ---------------------------------------------------------------------------
template<int Cin, int Cout, int K, int S, int P,
         int Hin, int Win, int Hout, int Wout,
         int CO, int CI, int TH>
__global__ void __launch_bounds__(256) conv_tiled_kernel(
    const float* __restrict__ src, float* __restrict__ dst,
    const float* __restrict__ w,  const float* __restrict__ bb,
    const float* __restrict__ g,  const float* __restrict__ be,
    const float* __restrict__ m,  const float* __restrict__ v)
{
    constexpr int TW = 32;
    constexpr int IH = (TH - 1) * S + K;
    constexpr int IW = (TW - 1) * S + K;
    constexpr int NO = CO / 8;
    constexpr int WTILES = Wout / TW;

    __shared__ float s_in[CI * IH * IW];
    __shared__ float s_w [CO * CI * K * K];

    const int n   = blockIdx.z;
    const int co0 = blockIdx.y * CO;
    const int ht  = blockIdx.x / WTILES;
    const int wt  = blockIdx.x % WTILES;
    const int hb  = ht * TH;
    const int wb  = wt * TW;

    const int pg = threadIdx.x & 31;   // w position in tile
    const int cg = threadIdx.x >> 5;   // channel group (0..7)

    float acc[NO][TH];
    #pragma unroll
    for (int no = 0; no < NO; no++)
        #pragma unroll
        for (int th = 0; th < TH; th++) acc[no][th] = 0.f;

    const int ihb = hb * S - P;
    const int iwb = wb * S - P;
    const float* srcn = src + (size_t)n * Cin * Hin * Win;

    for (int ci0 = 0; ci0 < Cin; ci0 += CI) {
        // stage input chunk (zero-filled OOB / tail channels)
        for (int i = threadIdx.x; i < CI * IH * IW; i += 256) {
            const int ci = i / (IH * IW);
            const int r  = (i / IW) % IH;
            const int c  = i % IW;
            const int gci = ci0 + ci;
            const int gh  = ihb + r;
            const int gw  = iwb + c;
            float val = 0.f;
            if (gci < Cin && (unsigned)gh < (unsigned)Hin &&
                (unsigned)gw < (unsigned)Win)
                val = srcn[(size_t)gci * (Hin * Win) + gh * Win + gw];
            s_in[i] = val;
        }
        // stage weights chunk
        for (int i = threadIdx.x; i < CO * CI * K * K; i += 256) {
            const int co = i / (CI * K * K);
            const int r  = i % (CI * K * K);
            const int ci = r / (K * K);
            const int kk = r % (K * K);
            const int gci = ci0 + ci;
            s_w[i] = (gci < Cin)
                ? w[((size_t)(co0 + co) * Cin + gci) * (K * K) + kk] : 0.f;
        }
        __syncthreads();

        for (int ci = 0; ci < CI; ci++) {
            const float* sp = s_in + ci * IH * IW;
            const float* wp = s_w + (cg * NO) * (CI * K * K) + ci * (K * K);
            for (int kh = 0; kh < K; kh++) {
                #pragma unroll
                for (int kw = 0; kw < K; kw++) {
                    float wr[NO];
                    #pragma unroll
                    for (int no = 0; no < NO; no++)
                        wr[no] = wp[no * (CI * K * K) + kh * K + kw];
                    #pragma unroll
                    for (int th = 0; th < TH; th++) {
                        const float x = sp[(th * S + kh) * IW + pg * S + kw];
                        #pragma unroll
                        for (int no = 0; no < NO; no++)
                            acc[no][th] = fmaf(x, wr[no], acc[no][th]);
                    }
                }
            }
        }
        __syncthreads();
    }

    // epilogue: BN + ReLU + store (coalesced over pg)
    #pragma unroll
    for (int no = 0; no < NO; no++) {
        const int c = co0 + cg * NO + no;
        const float s_   = g[c] * rsqrtf(v[c] + EPS_BN);
        const float bias = fmaf(bb[c] - m[c], s_, be[c]);
        #pragma unroll
        for (int th = 0; th < TH; th++)
            dst[((size_t)n * Cout + c) * (Hout * Wout) + (hb + th) * Wout + wb + pg]
                = fmaxf(fmaf(acc[no][th], s_, bias), 0.f);
    }
}

// ---------------------------------------------------------------------------
// L2 normalize f1 over channels: (n in [32,64) of g_feat3) -> g_f1n
// ---------------------------------------------------------------------------
__global__ void __launch_bounds__(256) l2norm_f1_kernel()
{
    const int HW = H3 * W3;
    int idx = blockIdx.x * blockDim.x + threadIdx.x;
    if (idx >= B * HW) return;
    const int hw = idx % HW;
    const int n  = idx / HW;
    const float* p = g_feat3 + ((size_t)(n + B) * 128) * HW + hw;
    float ss = 0.f;
    #pragma unroll 8
    for (int c = 0; c < 128; c++) { float x = p[(size_t)c * HW]; ss = fmaf(x, x, ss); }
    const float inv = 1.f / fmaxf(sqrtf(ss), EPS_L2);
    float* o = g_f1n + ((size_t)n * 128) * HW + hw;
    #pragma unroll 8
    for (int c = 0; c < 128; c++) o[(size_t)c * HW] = p[(size_t)c * HW] * inv;
}

// L2 normalize f0 and scatter into 4-padded buffer (pad region stays zero —
// g_f0n is zero-initialized at module load and pad cells never written)
__global__ void __launch_bounds__(256) l2norm_f0_pad_kernel()
{
    const int HW = H3 * W3;
    int idx = blockIdx.x * blockDim.x + threadIdx.x;
    if (idx >= B * HW) return;
    const int hw = idx % HW;
    const int n  = idx / HW;
    const int h  = hw / W3;
    const int w  = hw % W3;
    const float* p = g_feat3 + ((size_t)n * 128) * HW + hw;
    float ss = 0.f;
    #pragma unroll 8
    for (int c = 0; c < 128; c++) { float x = p[(size_t)c * HW]; ss = fmaf(x, x, ss); }
    const float inv = 1.f / fmaxf(sqrtf(ss), EPS_L2);
    float* o = g_f0n + ((size_t)n * 128 * HP + (h + 4)) * WP + (w + 4);
    #pragma unroll 8
    for (int c = 0; c < 128; c++) o[(size_t)c * HP * WP] = p[(size_t)c * HW] * inv;
}

// ---------------------------------------------------------------------------
// Correlation volume -> g_cat channels [0,81).
// ---------------------------------------------------------------------------
__global__ void __launch_bounds__(256) corr_kernel()
{
    __shared__ float s1[128 * 32];
    __shared__ float s0[128 * 40];
    const int wb = blockIdx.x * 32;
    const int h  = blockIdx.y;
    const int n  = blockIdx.z;
    const int tid = threadIdx.x;

    for (int i = tid; i < 128 * 32; i += 256) {
        const int c = i >> 5, w = i & 31;
        s1[i] = g_f1n[(((size_t)n * 128 + c) * H3 + h) * W3 + wb + w];
    }
    for (int dy = 0; dy < 9; dy++) {
        __syncthreads();
        for (int i = tid; i < 128 * 40; i += 256) {
            const int c = i / 40, w = i % 40;
            s0[i] = g_f0n[(((size_t)n * 128 + c) * HP + h + dy) * WP + wb + w];
        }
        __syncthreads();
        for (int it = tid; it < 288; it += 256) {
            const int dx = it >> 5, j = it & 31;
            float acc = 0.f;
            #pragma unroll 8
            for (int c = 0; c < 128; c++)
                acc = fmaf(s0[c * 40 + j + dx], s1[c * 32 + j], acc);
            g_cat[(((size_t)n * CCAT + dy * 9 + dx) * H3 + h) * W3 + wb + j] = acc;
        }
    }
}

// copy raw f1 into g_cat channels [81,209)
__global__ void __launch_bounds__(256) copy_f1_kernel()
{
    const int HW = H3 * W3;
    size_t i = (size_t)blockIdx.x * blockDim.x + threadIdx.x;
    if (i >= (size_t)B * 128 * HW) return;
    const size_t hw = i % HW;
    const size_t c  = (i / HW) % 128;
    const size_t n  = i / ((size_t)128 * HW);
    g_cat[((n * CCAT) + 81 + c) * HW + hw] =
        g_feat3[((n + B) * 128 + c) * HW + hw];
}

// ---------------------------------------------------------------------------
// global average pool: (32,256,24,32) -> (32,256)
// ---------------------------------------------------------------------------
__global__ void __launch_bounds__(256) avgpool_kernel(float* __restrict__ out)
{
    __shared__ float red[256];
    const int b = blockIdx.x;
    const float* p = g_x2 + (size_t)b * (H4 * W4);
    float s = 0.f;
    for (int i = threadIdx.x; i < H4 * W4; i += 256) s += p[i];
    red[threadIdx.x] = s;
    __syncthreads();
    for (int st = 128; st > 0; st >>= 1) {
        if (threadIdx.x < st) red[threadIdx.x] += red[threadIdx.x + st];
        __syncthreads();
    }
    if (threadIdx.x == 0) out[b] = red[0] * (1.f / (H4 * W4));
}

// ---------------------------------------------------------------------------
extern "C" void kernel_launch(void* const* d_in, const int* in_sizes, int n_in,
                              void* d_out, int out_size)
{
    const float* img0 = (const float*)d_in[0];
    const float* img1 = (const float*)d_in[1];
    const float* w1  = (const float*)d_in[2];  const float* b1  = (const float*)d_in[3];
    const float* g1  = (const float*)d_in[4];  const float* be1 = (const float*)d_in[5];
    const float* m1  = (const float*)d_in[6];  const float* v1  = (const float*)d_in[7];
    const float* w2  = (const float*)d_in[8];  const float* b2  = (const float*)d_in[9];
    const float* g2  = (const float*)d_in[10]; const float* be2 = (const float*)d_in[11];
    const float* m2  = (const float*)d_in[12]; const float* v2  = (const float*)d_in[13];
    const float* w3  = (const float*)d_in[14]; const float* b3  = (const float*)d_in[15];
    const float* g3  = (const float*)d_in[16]; const float* be3 = (const float*)d_in[17];
    const float* m3  = (const float*)d_in[18]; const float* v3  = (const float*)d_in[19];
    const float* wf1 = (const float*)d_in[20]; const float* bf1 = (const float*)d_in[21];
    const float* gf1 = (const float*)d_in[22]; const float* bef1= (const float*)d_in[23];
    const float* mf1 = (const float*)d_in[24]; const float* vf1 = (const float*)d_in[25];
    const float* wf2 = (const float*)d_in[26]; const float* bf2 = (const float*)d_in[27];
    const float* gf2 = (const float*)d_in[28]; const float* bef2= (const float*)d_in[29];
    const float* mf2 = (const float*)d_in[30]; const float* vf2 = (const float*)d_in[31];
    float* out = (float*)d_out;

    float *p_img, *p_f1, *p_f2, *p_f3, *p_cat, *p_x1, *p_x2;
    cudaGetSymbolAddress((void**)&p_img, g_img);
    cudaGetSymbolAddress((void**)&p_f1,  g_feat1);
    cudaGetSymbolAddress((void**)&p_f2,  g_feat2);
    cudaGetSymbolAddress((void**)&p_f3,  g_feat3);
    cudaGetSymbolAddress((void**)&p_cat, g_cat);
    cudaGetSymbolAddress((void**)&p_x1,  g_x1);
    cudaGetSymbolAddress((void**)&p_x2,  g_x2);

    // 1. concat images into batch-64 buffer
    {
        const size_t tot = (size_t)N2 * 3 * H0 * W0;
        copy_imgs_kernel<<<(unsigned)((tot + 255) / 256), 256>>>(img0, img1);
    }

    // 2. backbone (register-tiled)
    // conv1: 3->32, 7x7 s2. CO=32 (NO=4), CI=3 (single chunk), TH=8
    conv_tiled_kernel<3, 32, 7, 2, 3, H0, W0, H1, W1, 32, 3, 8>
        <<<dim3((H1 / 8) * (W1 / 32), 1, N2), 256>>>(p_img, p_f1, w1, b1, g1, be1, m1, v1);
    // conv2: 32->64, 5x5 s2. CO=64 (NO=8), CI=2, TH=8
    conv_tiled_kernel<32, 64, 5, 2, 2, H1, W1, H2, W2, 64, 2, 8>
        <<<dim3((H2 / 8) * (W2 / 32), 1, N2), 256>>>(p_f1, p_f2, w2, b2, g2, be2, m2, v2);
    // conv3: 64->128, 3x3 s2. CO=64 (NO=8), CI=4, TH=8
    conv_tiled_kernel<64, 128, 3, 2, 1, H2, W2, H3, W3, 64, 4, 8>
        <<<dim3((H3 / 8) * (W3 / 32), 2, N2), 256>>>(p_f2, p_f3, w3, b3, g3, be3, m3, v3);

    // 3. l2norm + correlation + concat
    {
        const int tot = B * H3 * W3;
        l2norm_f1_kernel<<<(tot + 255) / 256, 256>>>();
        l2norm_f0_pad_kernel<<<(tot + 255) / 256, 256>>>();
    }
    corr_kernel<<<dim3(W3 / 32, H3, B), 256>>>();
    {
        const size_t tot = (size_t)B * 128 * H3 * W3;
        copy_f1_kernel<<<(unsigned)((tot + 255) / 256), 256>>>();
    }

    // 4. fusion convs (register-tiled)
    // convf1: 209->256, 3x3 s2. CO=64 (NO=8), CI=4 (zero-pad tail), TH=8
    conv_tiled_kernel<CCAT, 256, 3, 2, 1, H3, W3, H4, W4, 64, 4, 8>
        <<<dim3((H4 / 8) * (W4 / 32), 4, B), 256>>>(p_cat, p_x1, wf1, bf1, gf1, bef1, mf1, vf1);
    // convf2: 256->256, 3x3 s1. CO=64 (NO=8), CI=8, TH=8
    conv_tiled_kernel<256, 256, 3, 1, 1, H4, W4, H4, W4, 64, 8, 8>
        <<<dim3((H4 / 8) * (W4 / 32), 4, B), 256>>>(p_x1, p_x2, wf2, bf2, gf2, bef2, mf2, vf2);

    // 5. global average pool -> (32,256)
    avgpool_kernel<<<B * 256, 256>>>(out);
}